// round 12
// baseline (speedup 1.0000x reference)
#include <cuda_runtime.h>
#include <cuda_bf16.h>
#include <math.h>
#include <stdint.h>

#define NLAYER 6
#define H      1024
#define H3     3072
#define NH     16
#define DH     64
#define FFD    4096
#define VOCAB  50257
#define SEQ    1024
#define BATCH  2
#define MTOK   (BATCH*SEQ)
#define BH     (BATCH*NH)

typedef __nv_bfloat16 bf16;

// -------- static device scratch --------
__device__ __align__(16) float g_x  [(size_t)MTOK*H];
__device__ __align__(16) float g_tmp[(size_t)MTOK*H];
__device__ __align__(16) float g_bqkv[(size_t)NLAYER*H3];

__device__ __align__(16) bf16 x_h[(size_t)MTOK*H],  x_l[(size_t)MTOK*H];
__device__ __align__(16) bf16 qkv_h[(size_t)MTOK*H3], qkv_l[(size_t)MTOK*H3];
__device__ __align__(16) bf16 c_h[(size_t)MTOK*H],  c_l[(size_t)MTOK*H];
__device__ __align__(16) bf16 vt_h[(size_t)BH*DH*SEQ], vt_l[(size_t)BH*DH*SEQ];
__device__ __align__(16) bf16 hh_h[(size_t)MTOK*FFD],  hh_l[(size_t)MTOK*FFD];

#define LQKV ((size_t)NLAYER*H3*H)
#define LHH  ((size_t)NLAYER*H*H)
#define LHF  ((size_t)NLAYER*H*FFD)
__device__ __align__(16) bf16 wqkv_h[LQKV], wqkv_l[LQKV];
__device__ __align__(16) bf16 wo_h[LHH], wo_l[LHH];
__device__ __align__(16) bf16 wi_h[LHF], wi_l[LHF], wf_h[LHF], wf_l[LHF];
__device__ __align__(16) bf16 tk_h[(size_t)VOCAB*H], tk_l[(size_t)VOCAB*H];

// ---------------- helpers ----------------
__device__ __forceinline__ uint32_t swz(uint32_t o) { return o ^ ((o >> 3) & 0x70); }
__device__ __forceinline__ uint32_t sptr(const void* p) {
    return (uint32_t)__cvta_generic_to_shared(p);
}
__device__ __forceinline__ float gelu_exact(float x) {
    return 0.5f * x * (1.f + erff(x * 0.70710678118654752440f));
}
__device__ __forceinline__ void split2(float v, bf16& h, bf16& l) {
    h = __float2bfloat16(v);
    l = __float2bfloat16(v - __bfloat162float(h));
}
__device__ __forceinline__ uint32_t packbf(bf16 a, bf16 b) {
    return (uint32_t)__bfloat16_as_ushort(a) | ((uint32_t)__bfloat16_as_ushort(b) << 16);
}

#define CP16(dst, src) asm volatile("cp.async.cg.shared.global [%0], [%1], 16;\n" :: "r"(dst), "l"(src) : "memory")
#define CP_COMMIT()    asm volatile("cp.async.commit_group;\n" ::: "memory")
#define CP_WAIT0()     asm volatile("cp.async.wait_group 0;\n" ::: "memory")
#define CP_WAIT1()     asm volatile("cp.async.wait_group 1;\n" ::: "memory")

#define LDSM4(r, a) asm volatile( \
    "ldmatrix.sync.aligned.m8n8.x4.shared.b16 {%0,%1,%2,%3}, [%4];" \
    : "=r"((r)[0]), "=r"((r)[1]), "=r"((r)[2]), "=r"((r)[3]) : "r"(a))
#define LDSM2(r, a) asm volatile( \
    "ldmatrix.sync.aligned.m8n8.x2.shared.b16 {%0,%1}, [%2];" \
    : "=r"((r)[0]), "=r"((r)[1]) : "r"(a))

#define MMA(d, a, b) asm volatile( \
    "mma.sync.aligned.m16n8k16.row.col.f32.bf16.bf16.f32 " \
    "{%0,%1,%2,%3}, {%4,%5,%6,%7}, {%8,%9}, {%0,%1,%2,%3};" \
    : "+f"((d)[0]), "+f"((d)[1]), "+f"((d)[2]), "+f"((d)[3]) \
    : "r"((a)[0]), "r"((a)[1]), "r"((a)[2]), "r"((a)[3]), "r"((b)[0]), "r"((b)[1]))

// ---------------- reductions ----------------
__device__ __forceinline__ float block_reduce_sum(float v) {
    __shared__ float sh[8];
    int lane = threadIdx.x & 31, w = threadIdx.x >> 5;
    #pragma unroll
    for (int o = 16; o; o >>= 1) v += __shfl_xor_sync(0xffffffffu, v, o);
    __syncthreads();
    if (lane == 0) sh[w] = v;
    __syncthreads();
    float t = 0.f;
    #pragma unroll
    for (int i = 0; i < 8; i++) t += sh[i];
    return t;
}

// ---------------- small kernels ----------------
__global__ __launch_bounds__(256) void embed_kernel(
    const int* __restrict__ ids, const float* __restrict__ tok,
    const float* __restrict__ pos, float* __restrict__ out)
{
    int m = blockIdx.x, t = threadIdx.x;
    int id = ids[m];
    int sp = m & (SEQ - 1);
    float4 a = ((const float4*)(tok + (size_t)id * H))[t];
    float4 p = ((const float4*)(pos + (size_t)sp * H))[t];
    a.x += p.x; a.y += p.y; a.z += p.z; a.w += p.w;
    ((float4*)(out + (size_t)m * H))[t] = a;
}

__global__ __launch_bounds__(256) void ln_kernel(
    const float* __restrict__ inp, const float* __restrict__ res,
    const float* __restrict__ g, const float* __restrict__ b,
    float* __restrict__ outf, bf16* __restrict__ oh, bf16* __restrict__ ol)
{
    int row = blockIdx.x, t = threadIdx.x;
    float4 v = ((const float4*)(inp + (size_t)row * H))[t];
    if (res) {
        float4 r = ((const float4*)(res + (size_t)row * H))[t];
        v.x += r.x; v.y += r.y; v.z += r.z; v.w += r.w;
    }
    float mean = block_reduce_sum(v.x + v.y + v.z + v.w) * (1.f / H);
    float dx = v.x - mean, dy = v.y - mean, dz = v.z - mean, dw = v.w - mean;
    float var = block_reduce_sum(dx*dx + dy*dy + dz*dz + dw*dw) * (1.f / H);
    float inv = rsqrtf(var + 1e-6f);
    float4 gg = ((const float4*)g)[t];
    float4 bb = ((const float4*)b)[t];
    float o[4] = {dx*inv*gg.x + bb.x, dy*inv*gg.y + bb.y,
                  dz*inv*gg.z + bb.z, dw*inv*gg.w + bb.w};
    ((float4*)(outf + (size_t)row * H))[t] = make_float4(o[0], o[1], o[2], o[3]);
    size_t ob = (size_t)row * H + t * 4;
    bf16 h0,h1,l0,l1,h2,h3,l2,l3;
    split2(o[0],h0,l0); split2(o[1],h1,l1);
    split2(o[2],h2,l2); split2(o[3],h3,l3);
    *(uint2*)(oh + ob) = make_uint2(packbf(h0,h1), packbf(h2,h3));
    *(uint2*)(ol + ob) = make_uint2(packbf(l0,l1), packbf(l2,l3));
}

// W[l][K,N] -> out[l][row0+N, K] split (vectorized 64x64 tiles)
__global__ __launch_bounds__(256) void wtrans_kernel(
    const float* __restrict__ W, bf16* __restrict__ oh, bf16* __restrict__ ol,
    int K, int N, long long loStride, int row0)
{
    __shared__ float t[64][65];
    int l = blockIdx.z;
    const float* Wl = W + (size_t)l * K * N;
    int n0 = blockIdx.x * 64, k0 = blockIdx.y * 64;
    int tid = threadIdx.x;
    #pragma unroll
    for (int i = 0; i < 4; i++) {
        int idx = tid + i * 256;
        int r = idx >> 4, c4 = (idx & 15) * 4;
        float4 v = *(const float4*)(Wl + (size_t)(k0 + r) * N + n0 + c4);
        t[r][c4] = v.x; t[r][c4+1] = v.y; t[r][c4+2] = v.z; t[r][c4+3] = v.w;
    }
    __syncthreads();
    size_t ob = (size_t)l * loStride + (size_t)row0 * K;
    #pragma unroll
    for (int i = 0; i < 4; i++) {
        int idx = tid + i * 256;
        int nr = idx >> 4, g = (idx & 15) * 4;
        float v0 = t[g][nr], v1 = t[g+1][nr], v2 = t[g+2][nr], v3 = t[g+3][nr];
        bf16 h0,h1,h2,h3,l0,l1,l2,l3;
        split2(v0,h0,l0); split2(v1,h1,l1); split2(v2,h2,l2); split2(v3,h3,l3);
        size_t o = ob + (size_t)(n0 + nr) * K + k0 + g;
        *(uint2*)(oh + o) = make_uint2(packbf(h0,h1), packbf(h2,h3));
        *(uint2*)(ol + o) = make_uint2(packbf(l0,l1), packbf(l2,l3));
    }
}

// vectorized elementwise split (n4 = n/4)
__global__ __launch_bounds__(256) void split_kernel(
    const float* __restrict__ in, bf16* __restrict__ oh, bf16* __restrict__ ol, size_t n4)
{
    for (size_t i = (size_t)blockIdx.x * blockDim.x + threadIdx.x; i < n4;
         i += (size_t)gridDim.x * blockDim.x) {
        float4 v = ((const float4*)in)[i];
        bf16 h0,h1,h2,h3,l0,l1,l2,l3;
        split2(v.x,h0,l0); split2(v.y,h1,l1); split2(v.z,h2,l2); split2(v.w,h3,l3);
        ((uint2*)oh)[i] = make_uint2(packbf(h0,h1), packbf(h2,h3));
        ((uint2*)ol)[i] = make_uint2(packbf(l0,l1), packbf(l2,l3));
    }
}

// bias concat: out[l][3H] = [bq|bk|bv]
__global__ __launch_bounds__(1024) void bcat_kernel(
    const float* __restrict__ bq, const float* __restrict__ bk,
    const float* __restrict__ bv, float* __restrict__ out)
{
    int l = blockIdx.x, t = threadIdx.x;
    out[(size_t)l*H3 + t]       = bq[(size_t)l*H + t];
    out[(size_t)l*H3 + H + t]   = bk[(size_t)l*H + t];
    out[(size_t)l*H3 + 2*H + t] = bv[(size_t)l*H + t];
}

// v split bf16 (stride H3) -> vt[bh][DH,SEQ] split
__global__ __launch_bounds__(1024) void vtrans_kernel(
    const bf16* __restrict__ vh, const bf16* __restrict__ vl,
    bf16* __restrict__ th, bf16* __restrict__ tl)
{
    __shared__ float tile[32][33];
    int d0 = blockIdx.x * 32, s0 = blockIdx.y * 32, bz = blockIdx.z;
    int bb = bz >> 4, hd = bz & 15;
    int tx = threadIdx.x, ty = threadIdx.y;
    size_t gi = (size_t)(bb * SEQ + s0 + ty) * H3 + hd * DH + d0 + tx;
    tile[ty][tx] = __bfloat162float(vh[gi]) + __bfloat162float(vl[gi]);
    __syncthreads();
    bf16 h, lo; split2(tile[tx][ty], h, lo);
    size_t o = ((size_t)bz * DH + d0 + ty) * SEQ + s0 + tx;
    th[o] = h; tl[o] = lo;
}

// ---------------- fused flash attention (split-bf16, online softmax) -------
__global__ __launch_bounds__(256, 1) void flash_kernel(
    const bf16* __restrict__ qh, const bf16* __restrict__ ql,
    const bf16* __restrict__ kh, const bf16* __restrict__ kl,
    const bf16* __restrict__ vth, const bf16* __restrict__ vtl,
    bf16* __restrict__ ch, bf16* __restrict__ cl)
{
    int qt = (int)gridDim.x - 1 - blockIdx.x;   // heavy tiles first
    int bh = blockIdx.y, bb = bh >> 4, hd = bh & 15;
    extern __shared__ char smem[];
    uint32_t sb = sptr(smem);
    int tid = threadIdx.x, wid = tid >> 5, lane = tid & 31;

    size_t qoff = ((size_t)bb * SEQ + qt * 128) * H3 + hd * 64;
    #pragma unroll
    for (int i = 0; i < 4; i++) {
        int idx = tid + i * 256;
        int r = idx >> 3, c = idx & 7;
        uint32_t so = swz(r * 128 + c * 16);
        CP16(sb + so,         qh + qoff + (size_t)r * H3 + c * 8);
        CP16(sb + 16384 + so, ql + qoff + (size_t)r * H3 + c * 8);
    }
    CP_COMMIT(); CP_WAIT0();
    __syncthreads();

    uint32_t QH[4][4], QL[4][4];
    int arow = lane & 15, asel = lane >> 4;
    #pragma unroll
    for (int kk = 0; kk < 4; kk++) {
        uint32_t off = swz((uint32_t)(wid * 16 + arow) * 128 + kk * 32 + asel * 16);
        LDSM4(QH[kk], sb + off);
        LDSM4(QL[kk], sb + 16384 + off);
    }
    __syncthreads();

    int nkt = 2 * (qt + 1);
    int wrow0 = qt * 128 + wid * 16;
    int r = lane >> 2, cq = (lane & 3) * 2;
    int grow0 = wrow0 + r, grow1 = wrow0 + r + 8;

    float m0 = -1e30f, m1 = -1e30f, l0 = 0.f, l1 = 0.f;
    float oacc[8][4];
    #pragma unroll
    for (int j = 0; j < 8; j++)
        #pragma unroll
        for (int c = 0; c < 4; c++) oacc[j][c] = 0.f;

    int brow = lane & 7, bsel = (lane >> 3) & 1;

    auto prefetch = [&](int kt) {
        uint32_t st = sb + (kt & 1) * 32768;
        int kv0 = kt * 64;
        #pragma unroll
        for (int i = 0; i < 2; i++) {
            int idx = tid + i * 256;
            int rr = idx >> 3, c = idx & 7;
            uint32_t so = swz(rr * 128 + c * 16);
            size_t kg = ((size_t)bb * SEQ + kv0 + rr) * H3 + hd * 64 + c * 8;
            CP16(st + so,         kh + kg);
            CP16(st + 8192 + so,  kl + kg);
            size_t vg = ((size_t)bh * DH + rr) * SEQ + kv0 + c * 8;
            CP16(st + 16384 + so, vth + vg);
            CP16(st + 24576 + so, vtl + vg);
        }
        CP_COMMIT();
    };

    prefetch(0);
    for (int kt = 0; kt < nkt; kt++) {
        if (kt + 1 < nkt) { prefetch(kt + 1); CP_WAIT1(); }
        else              { CP_WAIT0(); }
        __syncthreads();

        uint32_t st = sb + (kt & 1) * 32768;
        int kv0 = kt * 64;
        if (kv0 <= wrow0 + 15) {
            float sacc[8][4];
            #pragma unroll
            for (int j = 0; j < 8; j++)
                #pragma unroll
                for (int c = 0; c < 4; c++) sacc[j][c] = 0.f;
            #pragma unroll
            for (int kk = 0; kk < 4; kk++) {
                uint32_t bhf[8][2], blf[8][2];
                #pragma unroll
                for (int nj = 0; nj < 8; nj++) {
                    uint32_t off = swz((uint32_t)(nj*8 + brow) * 128 + kk*32 + bsel*16);
                    LDSM2(bhf[nj], st + off);
                    LDSM2(blf[nj], st + 8192 + off);
                }
                #pragma unroll
                for (int nj = 0; nj < 8; nj++) {
                    MMA(sacc[nj], QH[kk], bhf[nj]);
                    MMA(sacc[nj], QH[kk], blf[nj]);
                    MMA(sacc[nj], QL[kk], bhf[nj]);
                }
            }
            float mt0 = -1e30f, mt1 = -1e30f;
            #pragma unroll
            for (int nj = 0; nj < 8; nj++) {
                int j0 = kv0 + nj*8 + cq;
                float s0 = sacc[nj][0]*0.125f; if (j0   > grow0) s0 = -1e30f;
                float s1 = sacc[nj][1]*0.125f; if (j0+1 > grow0) s1 = -1e30f;
                float s2 = sacc[nj][2]*0.125f; if (j0   > grow1) s2 = -1e30f;
                float s3 = sacc[nj][3]*0.125f; if (j0+1 > grow1) s3 = -1e30f;
                sacc[nj][0]=s0; sacc[nj][1]=s1; sacc[nj][2]=s2; sacc[nj][3]=s3;
                mt0 = fmaxf(mt0, fmaxf(s0, s1));
                mt1 = fmaxf(mt1, fmaxf(s2, s3));
            }
            mt0 = fmaxf(mt0, __shfl_xor_sync(0xffffffffu, mt0, 1));
            mt0 = fmaxf(mt0, __shfl_xor_sync(0xffffffffu, mt0, 2));
            mt1 = fmaxf(mt1, __shfl_xor_sync(0xffffffffu, mt1, 1));
            mt1 = fmaxf(mt1, __shfl_xor_sync(0xffffffffu, mt1, 2));
            float mn0 = fmaxf(m0, mt0), mn1 = fmaxf(m1, mt1);
            float a0 = __expf(m0 - mn0), a1 = __expf(m1 - mn1);
            m0 = mn0; m1 = mn1;
            float ps0 = 0.f, ps1 = 0.f;
            #pragma unroll
            for (int nj = 0; nj < 8; nj++) {
                float p0 = __expf(sacc[nj][0] - mn0);
                float p1 = __expf(sacc[nj][1] - mn0);
                float p2 = __expf(sacc[nj][2] - mn1);
                float p3 = __expf(sacc[nj][3] - mn1);
                sacc[nj][0]=p0; sacc[nj][1]=p1; sacc[nj][2]=p2; sacc[nj][3]=p3;
                ps0 += p0 + p1; ps1 += p2 + p3;
            }
            ps0 += __shfl_xor_sync(0xffffffffu, ps0, 1);
            ps0 += __shfl_xor_sync(0xffffffffu, ps0, 2);
            ps1 += __shfl_xor_sync(0xffffffffu, ps1, 1);
            ps1 += __shfl_xor_sync(0xffffffffu, ps1, 2);
            l0 = l0 * a0 + ps0;
            l1 = l1 * a1 + ps1;
            #pragma unroll
            for (int dj = 0; dj < 8; dj++) {
                oacc[dj][0] *= a0; oacc[dj][1] *= a0;
                oacc[dj][2] *= a1; oacc[dj][3] *= a1;
            }
            #pragma unroll
            for (int t = 0; t < 4; t++) {
                uint32_t aH[4], aL[4];
                {
                    bf16 h0,h1,l0b,l1b;
                    split2(sacc[2*t][0],h0,l0b); split2(sacc[2*t][1],h1,l1b);
                    aH[0]=packbf(h0,h1); aL[0]=packbf(l0b,l1b);
                    split2(sacc[2*t][2],h0,l0b); split2(sacc[2*t][3],h1,l1b);
                    aH[1]=packbf(h0,h1); aL[1]=packbf(l0b,l1b);
                    split2(sacc[2*t+1][0],h0,l0b); split2(sacc[2*t+1][1],h1,l1b);
                    aH[2]=packbf(h0,h1); aL[2]=packbf(l0b,l1b);
                    split2(sacc[2*t+1][2],h0,l0b); split2(sacc[2*t+1][3],h1,l1b);
                    aH[3]=packbf(h0,h1); aL[3]=packbf(l0b,l1b);
                }
                #pragma unroll
                for (int dj = 0; dj < 8; dj++) {
                    uint32_t vh[2], vl[2];
                    uint32_t off = swz((uint32_t)(dj*8 + brow) * 128 + t*32 + bsel*16);
                    LDSM2(vh, st + 16384 + off);
                    LDSM2(vl, st + 24576 + off);
                    MMA(oacc[dj], aH, vh);
                    MMA(oacc[dj], aH, vl);
                    MMA(oacc[dj], aL, vh);
                }
            }
        }
        __syncthreads();
    }

    float il0 = 1.f / l0, il1 = 1.f / l1;
    size_t row0g = (size_t)bb * SEQ + grow0;
    size_t row1g = (size_t)bb * SEQ + grow1;
    #pragma unroll
    for (int dj = 0; dj < 8; dj++) {
        int col = hd * 64 + dj * 8 + cq;
        float v0 = oacc[dj][0] * il0, v1 = oacc[dj][1] * il0;
        float v2 = oacc[dj][2] * il1, v3 = oacc[dj][3] * il1;
        bf16 h0,h1,lo0,lo1;
        split2(v0,h0,lo0); split2(v1,h1,lo1);
        *(uint32_t*)(ch + row0g * H + col) = packbf(h0,h1);
        *(uint32_t*)(cl + row0g * H + col) = packbf(lo0,lo1);
        split2(v2,h0,lo0); split2(v3,h1,lo1);
        *(uint32_t*)(ch + row1g * H + col) = packbf(h0,h1);
        *(uint32_t*)(cl + row1g * H + col) = packbf(lo0,lo1);
    }
}

// ---------------- split-bf16 mma.sync GEMM (3-stage, 512 threads) ----------
// 16 warps, each owns 32x32 of the 128x128 CTA tile (mi=2, NJ=4).
// MODE 0: f32+bias | 1: split+bias | 2: gelu split+bias | 3: logits f32 (vocab guard)
template<int MODE>
__global__ __launch_bounds__(512, 1) void gemm_tc(
    const bf16* __restrict__ aH, const bf16* __restrict__ aL,
    const bf16* __restrict__ bH, const bf16* __restrict__ bL,
    const float* __restrict__ bias,
    float* __restrict__ Cf, bf16* __restrict__ Ch, bf16* __restrict__ Cl,
    long long lda, long long ldb, long long ldc, int Ks)
{
    constexpr int BN  = 128;
    constexpr int WN  = 32;              // cols per warp
    constexpr int NJ  = 4;               // n8 frags per warp
    constexpr int MI  = 2;               // m16 frags per warp
    constexpr int STG = 32768 + 2 * BN * 128;   // 64 KB per stage

    int n0 = blockIdx.x * 128;
    int m0 = blockIdx.y * 128;
    int rowmaxB = 1 << 30;
    aH += (size_t)m0 * lda; aL += (size_t)m0 * lda;
    bH += (size_t)n0 * ldb; bL += (size_t)n0 * ldb;
    if (Cf) Cf += (size_t)m0 * ldc + n0;
    if (Ch) { Ch += (size_t)m0 * ldc + n0; Cl += (size_t)m0 * ldc + n0; }
    if constexpr (MODE == 3) rowmaxB = VOCAB - 1 - n0;

    extern __shared__ char smem[];
    uint32_t sb = sptr(smem);
    int tid = threadIdx.x, wid = tid >> 5, lane = tid & 31;
    int wr = wid >> 2, wc = wid & 3;     // 4x4 warp grid, 32x32 each

    float acc[MI][NJ][4];
    #pragma unroll
    for (int i = 0; i < MI; i++)
        #pragma unroll
        for (int j = 0; j < NJ; j++)
            #pragma unroll
            for (int c = 0; c < 4; c++) acc[i][j][c] = 0.f;

    auto prefetch = [&](int t) {
        uint32_t st = sb + (t % 3) * STG;
        #pragma unroll
        for (int i = 0; i < 2; i++) {
            int idx = tid + i * 512;
            int r = idx >> 3, c = idx & 7;
            uint32_t so = swz(r * 128 + c * 16);
            size_t go = (size_t)r * lda + (size_t)t * 64 + c * 8;
            CP16(st + so,         aH + go);
            CP16(st + 16384 + so, aL + go);
        }
        #pragma unroll
        for (int i = 0; i < 2; i++) {
            int idx = tid + i * 512;
            int r = idx >> 3, c = idx & 7;
            int rc = r < rowmaxB ? r : rowmaxB;
            uint32_t so = swz(r * 128 + c * 16);
            size_t go = (size_t)rc * ldb + (size_t)t * 64 + c * 8;
            CP16(st + 32768 + so,          bH + go);
            CP16(st + 32768 + BN*128 + so, bL + go);
        }
        CP_COMMIT();
    };

    prefetch(0);
    prefetch(1);
    int arow = lane & 15, asel = lane >> 4;
    int b4row = ((lane >> 4) & 1) * 8 + (lane & 7);   // row within 16-row pair
    int b4sel = (lane >> 3) & 1;                       // k-half

    for (int t = 0; t < Ks; t++) {
        if (t + 1 < Ks) CP_WAIT1(); else CP_WAIT0();
        __syncthreads();
        if (t + 2 < Ks) prefetch(t + 2);

        uint32_t sA  = sb + (t % 3) * STG;
        uint32_t sAl = sA + 16384;
        uint32_t sB  = sA + 32768;
        uint32_t sBl = sB + BN * 128;

        #pragma unroll
        for (int kk = 0; kk < 4; kk++) {
            uint32_t ah[MI][4], al[MI][4], bh[NJ][2], bl[NJ][2];
            #pragma unroll
            for (int mi = 0; mi < MI; mi++) {
                uint32_t off = swz((uint32_t)(wr*32 + mi*16 + arow) * 128 + kk*32 + asel*16);
                LDSM4(ah[mi], sA  + off);
                LDSM4(al[mi], sAl + off);
            }
            #pragma unroll
            for (int p = 0; p < NJ/2; p++) {
                uint32_t rh[4], rl[4];
                uint32_t off = swz((uint32_t)(wc*WN + p*16 + b4row) * 128 + kk*32 + b4sel*16);
                LDSM4(rh, sB  + off);
                LDSM4(rl, sBl + off);
                bh[2*p][0]=rh[0]; bh[2*p][1]=rh[1]; bh[2*p+1][0]=rh[2]; bh[2*p+1][1]=rh[3];
                bl[2*p][0]=rl[0]; bl[2*p][1]=rl[1]; bl[2*p+1][0]=rl[2]; bl[2*p+1][1]=rl[3];
            }
            #pragma unroll
            for (int mi = 0; mi < MI; mi++)
                #pragma unroll
                for (int nj = 0; nj < NJ; nj++) {
                    MMA(acc[mi][nj], ah[mi], bh[nj]);
                    MMA(acc[mi][nj], ah[mi], bl[nj]);
                    MMA(acc[mi][nj], al[mi], bh[nj]);
                }
        }
    }

    int r_lo = lane >> 2, cq = (lane & 3) * 2;
    #pragma unroll
    for (int mi = 0; mi < MI; mi++) {
        #pragma unroll
        for (int nj = 0; nj < NJ; nj++) {
            int cc = wc*WN + nj*8 + cq;
            #pragma unroll
            for (int half = 0; half < 2; half++) {
                int rr = wr*32 + mi*16 + r_lo + half*8;
                float v0 = acc[mi][nj][half*2], v1 = acc[mi][nj][half*2+1];
                if constexpr (MODE == 3) {
                    if (n0 + cc     < VOCAB) Cf[(size_t)rr*ldc + cc]     = v0;
                    if (n0 + cc + 1 < VOCAB) Cf[(size_t)rr*ldc + cc + 1] = v1;
                } else if constexpr (MODE == 0) {
                    v0 += bias[n0 + cc]; v1 += bias[n0 + cc + 1];
                    *(float2*)(Cf + (size_t)rr*ldc + cc) = make_float2(v0, v1);
                } else {
                    v0 += bias[n0 + cc]; v1 += bias[n0 + cc + 1];
                    if constexpr (MODE == 2) { v0 = gelu_exact(v0); v1 = gelu_exact(v1); }
                    bf16 h0,h1,l0,l1;
                    split2(v0,h0,l0); split2(v1,h1,l1);
                    *(uint32_t*)(Ch + (size_t)rr*ldc + cc) = packbf(h0,h1);
                    *(uint32_t*)(Cl + (size_t)rr*ldc + cc) = packbf(l0,l1);
                }
            }
        }
    }
}

// ------------------------------- launch ------------------------------------
#define SMEM128 (3*(32768 + 2*128*128))   // 192 KB, 3-stage
#define SMEMFL  65536

extern "C" void kernel_launch(void* const* d_in, const int* in_sizes, int n_in,
                              void* d_out, int out_size)
{
    const int*   ids  = (const int*)  d_in[0];
    const float* tok  = (const float*)d_in[1];
    const float* pos  = (const float*)d_in[2];
    const float* ln0g = (const float*)d_in[3];
    const float* ln0b = (const float*)d_in[4];
    const float* Wq = (const float*)d_in[5];  const float* bq = (const float*)d_in[6];
    const float* Wk = (const float*)d_in[7];  const float* bk = (const float*)d_in[8];
    const float* Wv = (const float*)d_in[9];  const float* bv = (const float*)d_in[10];
    const float* Wo = (const float*)d_in[11]; const float* bo = (const float*)d_in[12];
    const float* ln1g = (const float*)d_in[13]; const float* ln1b = (const float*)d_in[14];
    const float* Wi = (const float*)d_in[15]; const float* bi = (const float*)d_in[16];
    const float* Wf = (const float*)d_in[17]; const float* bf_ = (const float*)d_in[18];
    const float* ln2g = (const float*)d_in[19]; const float* ln2b = (const float*)d_in[20];
    float* logits = (float*)d_out;

    cudaFuncSetAttribute(gemm_tc<0>, cudaFuncAttributeMaxDynamicSharedMemorySize, SMEM128);
    cudaFuncSetAttribute(gemm_tc<1>, cudaFuncAttributeMaxDynamicSharedMemorySize, SMEM128);
    cudaFuncSetAttribute(gemm_tc<2>, cudaFuncAttributeMaxDynamicSharedMemorySize, SMEM128);
    cudaFuncSetAttribute(gemm_tc<3>, cudaFuncAttributeMaxDynamicSharedMemorySize, SMEM128);
    cudaFuncSetAttribute(flash_kernel, cudaFuncAttributeMaxDynamicSharedMemorySize, SMEMFL);

    float *px, *ptmp, *pbqkv;
    bf16 *pxh, *pxl, *pqkvh, *pqkvl, *pch, *pcl, *pvth, *pvtl, *phh, *phl;
    bf16 *pwqkvh, *pwqkvl, *pwoh, *pwol;
    bf16 *pwih, *pwil, *pwfh, *pwfl, *ptkh, *ptkl;
    cudaGetSymbolAddress((void**)&px, g_x);      cudaGetSymbolAddress((void**)&ptmp, g_tmp);
    cudaGetSymbolAddress((void**)&pbqkv, g_bqkv);
    cudaGetSymbolAddress((void**)&pxh, x_h);     cudaGetSymbolAddress((void**)&pxl, x_l);
    cudaGetSymbolAddress((void**)&pqkvh, qkv_h); cudaGetSymbolAddress((void**)&pqkvl, qkv_l);
    cudaGetSymbolAddress((void**)&pch, c_h);     cudaGetSymbolAddress((void**)&pcl, c_l);
    cudaGetSymbolAddress((void**)&pvth, vt_h);   cudaGetSymbolAddress((void**)&pvtl, vt_l);
    cudaGetSymbolAddress((void**)&phh, hh_h);    cudaGetSymbolAddress((void**)&phl, hh_l);
    cudaGetSymbolAddress((void**)&pwqkvh, wqkv_h); cudaGetSymbolAddress((void**)&pwqkvl, wqkv_l);
    cudaGetSymbolAddress((void**)&pwoh, wo_h);   cudaGetSymbolAddress((void**)&pwol, wo_l);
    cudaGetSymbolAddress((void**)&pwih, wi_h);   cudaGetSymbolAddress((void**)&pwil, wi_l);
    cudaGetSymbolAddress((void**)&pwfh, wf_h);   cudaGetSymbolAddress((void**)&pwfl, wf_l);
    cudaGetSymbolAddress((void**)&ptkh, tk_h);   cudaGetSymbolAddress((void**)&ptkl, tk_l);

    // ---- weight prep ----
    wtrans_kernel<<<dim3(16, 16, 6), 256>>>(Wq, pwqkvh, pwqkvl, H, H, (long long)H3*H, 0);
    wtrans_kernel<<<dim3(16, 16, 6), 256>>>(Wk, pwqkvh, pwqkvl, H, H, (long long)H3*H, H);
    wtrans_kernel<<<dim3(16, 16, 6), 256>>>(Wv, pwqkvh, pwqkvl, H, H, (long long)H3*H, 2*H);
    wtrans_kernel<<<dim3(16, 16, 6), 256>>>(Wo, pwoh, pwol, H, H, (long long)H*H, 0);
    wtrans_kernel<<<dim3(64, 16, 6), 256>>>(Wi, pwih, pwil, H, FFD, (long long)H*FFD, 0);
    wtrans_kernel<<<dim3(16, 64, 6), 256>>>(Wf, pwfh, pwfl, FFD, H, (long long)FFD*H, 0);
    bcat_kernel<<<NLAYER, 1024>>>(bq, bk, bv, pbqkv);
    split_kernel<<<2048, 256>>>(tok, ptkh, ptkl, (size_t)VOCAB * H / 4);

    embed_kernel<<<MTOK, 256>>>(ids, tok, pos, ptmp);
    ln_kernel<<<MTOK, 256>>>(ptmp, nullptr, ln0g, ln0b, px, pxh, pxl);

    dim3 g_hh(8, 16);
    for (int l = 0; l < NLAYER; l++) {
        size_t oQKV = (size_t)l * H3 * H, oHH = (size_t)l * H * H, oHF = (size_t)l * H * FFD;

        gemm_tc<1><<<dim3(24, 16), 512, SMEM128>>>(pxh, pxl, pwqkvh+oQKV, pwqkvl+oQKV,
                                                   pbqkv + (size_t)l*H3,
                                                   nullptr, pqkvh, pqkvl, H, H, H3, 16);
        vtrans_kernel<<<dim3(2, 32, 32), dim3(32, 32)>>>(pqkvh + 2*H, pqkvl + 2*H, pvth, pvtl);

        flash_kernel<<<dim3(SEQ/128, BH), 256, SMEMFL>>>(pqkvh, pqkvl, pqkvh + H, pqkvl + H,
                                                         pvth, pvtl, pch, pcl);

        gemm_tc<0><<<g_hh, 512, SMEM128>>>(pch, pcl, pwoh+oHH, pwol+oHH, bo + (size_t)l*H,
                                           ptmp, nullptr, nullptr, H, H, H, 16);
        ln_kernel<<<MTOK, 256>>>(ptmp, px, ln1g + (size_t)l*H, ln1b + (size_t)l*H, px, pxh, pxl);

        gemm_tc<2><<<dim3(32, 16), 512, SMEM128>>>(pxh, pxl, pwih+oHF, pwil+oHF, bi + (size_t)l*FFD,
                                                   nullptr, phh, phl, H, H, FFD, 16);
        gemm_tc<0><<<g_hh, 512, SMEM128>>>(phh, phl, pwfh+oHF, pwfl+oHF, bf_ + (size_t)l*H,
                                           ptmp, nullptr, nullptr, FFD, FFD, H, 64);
        ln_kernel<<<MTOK, 256>>>(ptmp, px, ln2g + (size_t)l*H, ln2b + (size_t)l*H, px, pxh, pxl);
    }

    gemm_tc<3><<<dim3((VOCAB + 127)/128, 16), 512, SMEM128>>>(
        pxh, pxl, ptkh, ptkl, nullptr, logits, nullptr, nullptr, H, H, VOCAB, 16);
}

// round 13
// speedup vs baseline: 1.0702x; 1.0702x over previous
#include <cuda_runtime.h>
#include <cuda_bf16.h>
#include <math.h>
#include <stdint.h>

#define NLAYER 6
#define H      1024
#define H3     3072
#define NH     16
#define DH     64
#define FFD    4096
#define VOCAB  50257
#define SEQ    1024
#define BATCH  2
#define MTOK   (BATCH*SEQ)
#define BH     (BATCH*NH)

typedef __nv_bfloat16 bf16;

// -------- static device scratch --------
__device__ __align__(16) float g_x  [(size_t)MTOK*H];
__device__ __align__(16) float g_tmp[(size_t)MTOK*H];
__device__ __align__(16) float g_bqkv[(size_t)NLAYER*H3];

__device__ __align__(16) bf16 x_h[(size_t)MTOK*H],  x_l[(size_t)MTOK*H];
__device__ __align__(16) bf16 qkv_h[(size_t)MTOK*H3], qkv_l[(size_t)MTOK*H3];
__device__ __align__(16) bf16 c_h[(size_t)MTOK*H],  c_l[(size_t)MTOK*H];
__device__ __align__(16) bf16 hh_h[(size_t)MTOK*FFD],  hh_l[(size_t)MTOK*FFD];

#define LQKV ((size_t)NLAYER*H3*H)
#define LHH  ((size_t)NLAYER*H*H)
#define LHF  ((size_t)NLAYER*H*FFD)
__device__ __align__(16) bf16 wqkv_h[LQKV], wqkv_l[LQKV];
__device__ __align__(16) bf16 wo_h[LHH], wo_l[LHH];
__device__ __align__(16) bf16 wi_h[LHF], wi_l[LHF], wf_h[LHF], wf_l[LHF];
__device__ __align__(16) bf16 tk_h[(size_t)VOCAB*H], tk_l[(size_t)VOCAB*H];

// ---------------- helpers ----------------
__device__ __forceinline__ uint32_t swz(uint32_t o) { return o ^ ((o >> 3) & 0x70); }
__device__ __forceinline__ uint32_t sptr(const void* p) {
    return (uint32_t)__cvta_generic_to_shared(p);
}
__device__ __forceinline__ float gelu_exact(float x) {
    return 0.5f * x * (1.f + erff(x * 0.70710678118654752440f));
}
__device__ __forceinline__ void split2(float v, bf16& h, bf16& l) {
    h = __float2bfloat16(v);
    l = __float2bfloat16(v - __bfloat162float(h));
}
__device__ __forceinline__ uint32_t packbf(bf16 a, bf16 b) {
    return (uint32_t)__bfloat16_as_ushort(a) | ((uint32_t)__bfloat16_as_ushort(b) << 16);
}

#define CP16(dst, src) asm volatile("cp.async.cg.shared.global [%0], [%1], 16;\n" :: "r"(dst), "l"(src) : "memory")
#define CP_COMMIT()    asm volatile("cp.async.commit_group;\n" ::: "memory")
#define CP_WAIT0()     asm volatile("cp.async.wait_group 0;\n" ::: "memory")
#define CP_WAIT1()     asm volatile("cp.async.wait_group 1;\n" ::: "memory")

#define LDSM4(r, a) asm volatile( \
    "ldmatrix.sync.aligned.m8n8.x4.shared.b16 {%0,%1,%2,%3}, [%4];" \
    : "=r"((r)[0]), "=r"((r)[1]), "=r"((r)[2]), "=r"((r)[3]) : "r"(a))
#define LDSM2(r, a) asm volatile( \
    "ldmatrix.sync.aligned.m8n8.x2.shared.b16 {%0,%1}, [%2];" \
    : "=r"((r)[0]), "=r"((r)[1]) : "r"(a))
#define LDSM2T(r, a) asm volatile( \
    "ldmatrix.sync.aligned.m8n8.x2.trans.shared.b16 {%0,%1}, [%2];" \
    : "=r"((r)[0]), "=r"((r)[1]) : "r"(a))

#define MMA(d, a, b) asm volatile( \
    "mma.sync.aligned.m16n8k16.row.col.f32.bf16.bf16.f32 " \
    "{%0,%1,%2,%3}, {%4,%5,%6,%7}, {%8,%9}, {%0,%1,%2,%3};" \
    : "+f"((d)[0]), "+f"((d)[1]), "+f"((d)[2]), "+f"((d)[3]) \
    : "r"((a)[0]), "r"((a)[1]), "r"((a)[2]), "r"((a)[3]), "r"((b)[0]), "r"((b)[1]))

// ---------------- reductions ----------------
__device__ __forceinline__ float block_reduce_sum(float v) {
    __shared__ float sh[8];
    int lane = threadIdx.x & 31, w = threadIdx.x >> 5;
    #pragma unroll
    for (int o = 16; o; o >>= 1) v += __shfl_xor_sync(0xffffffffu, v, o);
    __syncthreads();
    if (lane == 0) sh[w] = v;
    __syncthreads();
    float t = 0.f;
    #pragma unroll
    for (int i = 0; i < 8; i++) t += sh[i];
    return t;
}

// ---------------- small kernels ----------------
__global__ __launch_bounds__(256) void embed_kernel(
    const int* __restrict__ ids, const float* __restrict__ tok,
    const float* __restrict__ pos, float* __restrict__ out)
{
    int m = blockIdx.x, t = threadIdx.x;
    int id = ids[m];
    int sp = m & (SEQ - 1);
    float4 a = ((const float4*)(tok + (size_t)id * H))[t];
    float4 p = ((const float4*)(pos + (size_t)sp * H))[t];
    a.x += p.x; a.y += p.y; a.z += p.z; a.w += p.w;
    ((float4*)(out + (size_t)m * H))[t] = a;
}

__global__ __launch_bounds__(256) void ln_kernel(
    const float* __restrict__ inp, const float* __restrict__ res,
    const float* __restrict__ g, const float* __restrict__ b,
    float* __restrict__ outf, bf16* __restrict__ oh, bf16* __restrict__ ol)
{
    int row = blockIdx.x, t = threadIdx.x;
    float4 v = ((const float4*)(inp + (size_t)row * H))[t];
    if (res) {
        float4 r = ((const float4*)(res + (size_t)row * H))[t];
        v.x += r.x; v.y += r.y; v.z += r.z; v.w += r.w;
    }
    float mean = block_reduce_sum(v.x + v.y + v.z + v.w) * (1.f / H);
    float dx = v.x - mean, dy = v.y - mean, dz = v.z - mean, dw = v.w - mean;
    float var = block_reduce_sum(dx*dx + dy*dy + dz*dz + dw*dw) * (1.f / H);
    float inv = rsqrtf(var + 1e-6f);
    float4 gg = ((const float4*)g)[t];
    float4 bb = ((const float4*)b)[t];
    float o[4] = {dx*inv*gg.x + bb.x, dy*inv*gg.y + bb.y,
                  dz*inv*gg.z + bb.z, dw*inv*gg.w + bb.w};
    ((float4*)(outf + (size_t)row * H))[t] = make_float4(o[0], o[1], o[2], o[3]);
    size_t ob = (size_t)row * H + t * 4;
    bf16 h0,h1,l0,l1,h2,h3,l2,l3;
    split2(o[0],h0,l0); split2(o[1],h1,l1);
    split2(o[2],h2,l2); split2(o[3],h3,l3);
    *(uint2*)(oh + ob) = make_uint2(packbf(h0,h1), packbf(h2,h3));
    *(uint2*)(ol + ob) = make_uint2(packbf(l0,l1), packbf(l2,l3));
}

// W[l][K,N] -> out[l][row0+N, K] split (vectorized 64x64 tiles)
__global__ __launch_bounds__(256) void wtrans_kernel(
    const float* __restrict__ W, bf16* __restrict__ oh, bf16* __restrict__ ol,
    int K, int N, long long loStride, int row0)
{
    __shared__ float t[64][65];
    int l = blockIdx.z;
    const float* Wl = W + (size_t)l * K * N;
    int n0 = blockIdx.x * 64, k0 = blockIdx.y * 64;
    int tid = threadIdx.x;
    #pragma unroll
    for (int i = 0; i < 4; i++) {
        int idx = tid + i * 256;
        int r = idx >> 4, c4 = (idx & 15) * 4;
        float4 v = *(const float4*)(Wl + (size_t)(k0 + r) * N + n0 + c4);
        t[r][c4] = v.x; t[r][c4+1] = v.y; t[r][c4+2] = v.z; t[r][c4+3] = v.w;
    }
    __syncthreads();
    size_t ob = (size_t)l * loStride + (size_t)row0 * K;
    #pragma unroll
    for (int i = 0; i < 4; i++) {
        int idx = tid + i * 256;
        int nr = idx >> 4, g = (idx & 15) * 4;
        float v0 = t[g][nr], v1 = t[g+1][nr], v2 = t[g+2][nr], v3 = t[g+3][nr];
        bf16 h0,h1,h2,h3,l0,l1,l2,l3;
        split2(v0,h0,l0); split2(v1,h1,l1); split2(v2,h2,l2); split2(v3,h3,l3);
        size_t o = ob + (size_t)(n0 + nr) * K + k0 + g;
        *(uint2*)(oh + o) = make_uint2(packbf(h0,h1), packbf(h2,h3));
        *(uint2*)(ol + o) = make_uint2(packbf(l0,l1), packbf(l2,l3));
    }
}

// merged QKV transpose: z = l*3 + which
__global__ __launch_bounds__(256) void wtransqkv_kernel(
    const float* __restrict__ Wq, const float* __restrict__ Wk,
    const float* __restrict__ Wv, bf16* __restrict__ oh, bf16* __restrict__ ol)
{
    __shared__ float t[64][65];
    int z = blockIdx.z;
    int l = z / 3, which = z % 3;
    const float* W = (which == 0) ? Wq : (which == 1) ? Wk : Wv;
    const float* Wl = W + (size_t)l * H * H;
    int n0 = blockIdx.x * 64, k0 = blockIdx.y * 64;
    int tid = threadIdx.x;
    #pragma unroll
    for (int i = 0; i < 4; i++) {
        int idx = tid + i * 256;
        int r = idx >> 4, c4 = (idx & 15) * 4;
        float4 v = *(const float4*)(Wl + (size_t)(k0 + r) * H + n0 + c4);
        t[r][c4] = v.x; t[r][c4+1] = v.y; t[r][c4+2] = v.z; t[r][c4+3] = v.w;
    }
    __syncthreads();
    size_t ob = (size_t)l * H3 * H + (size_t)(which * H) * H;
    #pragma unroll
    for (int i = 0; i < 4; i++) {
        int idx = tid + i * 256;
        int nr = idx >> 4, g = (idx & 15) * 4;
        float v0 = t[g][nr], v1 = t[g+1][nr], v2 = t[g+2][nr], v3 = t[g+3][nr];
        bf16 h0,h1,h2,h3,l0,l1,l2,l3;
        split2(v0,h0,l0); split2(v1,h1,l1); split2(v2,h2,l2); split2(v3,h3,l3);
        size_t o = ob + (size_t)(n0 + nr) * H + k0 + g;
        *(uint2*)(oh + o) = make_uint2(packbf(h0,h1), packbf(h2,h3));
        *(uint2*)(ol + o) = make_uint2(packbf(l0,l1), packbf(l2,l3));
    }
}

// vectorized elementwise split (n4 = n/4)
__global__ __launch_bounds__(256) void split_kernel(
    const float* __restrict__ in, bf16* __restrict__ oh, bf16* __restrict__ ol, size_t n4)
{
    for (size_t i = (size_t)blockIdx.x * blockDim.x + threadIdx.x; i < n4;
         i += (size_t)gridDim.x * blockDim.x) {
        float4 v = ((const float4*)in)[i];
        bf16 h0,h1,h2,h3,l0,l1,l2,l3;
        split2(v.x,h0,l0); split2(v.y,h1,l1); split2(v.z,h2,l2); split2(v.w,h3,l3);
        ((uint2*)oh)[i] = make_uint2(packbf(h0,h1), packbf(h2,h3));
        ((uint2*)ol)[i] = make_uint2(packbf(l0,l1), packbf(l2,l3));
    }
}

// bias concat: out[l][3H] = [bq|bk|bv]
__global__ __launch_bounds__(1024) void bcat_kernel(
    const float* __restrict__ bq, const float* __restrict__ bk,
    const float* __restrict__ bv, float* __restrict__ out)
{
    int l = blockIdx.x, t = threadIdx.x;
    out[(size_t)l*H3 + t]       = bq[(size_t)l*H + t];
    out[(size_t)l*H3 + H + t]   = bk[(size_t)l*H + t];
    out[(size_t)l*H3 + 2*H + t] = bv[(size_t)l*H + t];
}

// ---------------- fused flash attention (split-bf16, online softmax) -------
// V consumed directly from qkv (row-major [seq, dh], stride H3) via trans ldmatrix.
__global__ __launch_bounds__(256, 1) void flash_kernel(
    const bf16* __restrict__ qh, const bf16* __restrict__ ql,
    const bf16* __restrict__ kh, const bf16* __restrict__ kl,
    const bf16* __restrict__ vh, const bf16* __restrict__ vl,
    bf16* __restrict__ ch, bf16* __restrict__ cl)
{
    int qt = (int)gridDim.x - 1 - blockIdx.x;   // heavy tiles first
    int bh = blockIdx.y, bb = bh >> 4, hd = bh & 15;
    extern __shared__ char smem[];
    uint32_t sb = sptr(smem);
    int tid = threadIdx.x, wid = tid >> 5, lane = tid & 31;

    size_t qoff = ((size_t)bb * SEQ + qt * 128) * H3 + hd * 64;
    #pragma unroll
    for (int i = 0; i < 4; i++) {
        int idx = tid + i * 256;
        int r = idx >> 3, c = idx & 7;
        uint32_t so = swz(r * 128 + c * 16);
        CP16(sb + so,         qh + qoff + (size_t)r * H3 + c * 8);
        CP16(sb + 16384 + so, ql + qoff + (size_t)r * H3 + c * 8);
    }
    CP_COMMIT(); CP_WAIT0();
    __syncthreads();

    uint32_t QH[4][4], QL[4][4];
    int arow = lane & 15, asel = lane >> 4;
    #pragma unroll
    for (int kk = 0; kk < 4; kk++) {
        uint32_t off = swz((uint32_t)(wid * 16 + arow) * 128 + kk * 32 + asel * 16);
        LDSM4(QH[kk], sb + off);
        LDSM4(QL[kk], sb + 16384 + off);
    }
    __syncthreads();

    int nkt = 2 * (qt + 1);
    int wrow0 = qt * 128 + wid * 16;
    int r = lane >> 2, cq = (lane & 3) * 2;
    int grow0 = wrow0 + r, grow1 = wrow0 + r + 8;

    float m0 = -1e30f, m1 = -1e30f, l0 = 0.f, l1 = 0.f;
    float oacc[8][4];
    #pragma unroll
    for (int j = 0; j < 8; j++)
        #pragma unroll
        for (int c = 0; c < 4; c++) oacc[j][c] = 0.f;

    int brow = lane & 7, bsel = (lane >> 3) & 1;
    int vrow = lane & 15;   // trans-ldmatrix k-row supplier

    // kv stage 32KB: [Kh 8K][Kl 8K][Vh 8K][Vl 8K]; K rows=seq(k), V rows=seq(k)
    auto prefetch = [&](int kt) {
        uint32_t st = sb + (kt & 1) * 32768;
        int kv0 = kt * 64;
        #pragma unroll
        for (int i = 0; i < 2; i++) {
            int idx = tid + i * 256;
            int rr = idx >> 3, c = idx & 7;
            uint32_t so = swz(rr * 128 + c * 16);
            size_t g = ((size_t)bb * SEQ + kv0 + rr) * H3 + hd * 64 + c * 8;
            CP16(st + so,         kh + g);
            CP16(st + 8192 + so,  kl + g);
            CP16(st + 16384 + so, vh + g);
            CP16(st + 24576 + so, vl + g);
        }
        CP_COMMIT();
    };

    prefetch(0);
    for (int kt = 0; kt < nkt; kt++) {
        if (kt + 1 < nkt) { prefetch(kt + 1); CP_WAIT1(); }
        else              { CP_WAIT0(); }
        __syncthreads();

        uint32_t st = sb + (kt & 1) * 32768;
        int kv0 = kt * 64;
        if (kv0 <= wrow0 + 15) {
            float sacc[8][4];
            #pragma unroll
            for (int j = 0; j < 8; j++)
                #pragma unroll
                for (int c = 0; c < 4; c++) sacc[j][c] = 0.f;
            #pragma unroll
            for (int kk = 0; kk < 4; kk++) {
                uint32_t bhf[8][2], blf[8][2];
                #pragma unroll
                for (int nj = 0; nj < 8; nj++) {
                    uint32_t off = swz((uint32_t)(nj*8 + brow) * 128 + kk*32 + bsel*16);
                    LDSM2(bhf[nj], st + off);
                    LDSM2(blf[nj], st + 8192 + off);
                }
                #pragma unroll
                for (int nj = 0; nj < 8; nj++) {
                    MMA(sacc[nj], QH[kk], bhf[nj]);
                    MMA(sacc[nj], QH[kk], blf[nj]);
                    MMA(sacc[nj], QL[kk], bhf[nj]);
                }
            }
            float mt0 = -1e30f, mt1 = -1e30f;
            #pragma unroll
            for (int nj = 0; nj < 8; nj++) {
                int j0 = kv0 + nj*8 + cq;
                float s0 = sacc[nj][0]*0.125f; if (j0   > grow0) s0 = -1e30f;
                float s1 = sacc[nj][1]*0.125f; if (j0+1 > grow0) s1 = -1e30f;
                float s2 = sacc[nj][2]*0.125f; if (j0   > grow1) s2 = -1e30f;
                float s3 = sacc[nj][3]*0.125f; if (j0+1 > grow1) s3 = -1e30f;
                sacc[nj][0]=s0; sacc[nj][1]=s1; sacc[nj][2]=s2; sacc[nj][3]=s3;
                mt0 = fmaxf(mt0, fmaxf(s0, s1));
                mt1 = fmaxf(mt1, fmaxf(s2, s3));
            }
            mt0 = fmaxf(mt0, __shfl_xor_sync(0xffffffffu, mt0, 1));
            mt0 = fmaxf(mt0, __shfl_xor_sync(0xffffffffu, mt0, 2));
            mt1 = fmaxf(mt1, __shfl_xor_sync(0xffffffffu, mt1, 1));
            mt1 = fmaxf(mt1, __shfl_xor_sync(0xffffffffu, mt1, 2));
            float mn0 = fmaxf(m0, mt0), mn1 = fmaxf(m1, mt1);
            float a0 = __expf(m0 - mn0), a1 = __expf(m1 - mn1);
            m0 = mn0; m1 = mn1;
            float ps0 = 0.f, ps1 = 0.f;
            #pragma unroll
            for (int nj = 0; nj < 8; nj++) {
                float p0 = __expf(sacc[nj][0] - mn0);
                float p1 = __expf(sacc[nj][1] - mn0);
                float p2 = __expf(sacc[nj][2] - mn1);
                float p3 = __expf(sacc[nj][3] - mn1);
                sacc[nj][0]=p0; sacc[nj][1]=p1; sacc[nj][2]=p2; sacc[nj][3]=p3;
                ps0 += p0 + p1; ps1 += p2 + p3;
            }
            ps0 += __shfl_xor_sync(0xffffffffu, ps0, 1);
            ps0 += __shfl_xor_sync(0xffffffffu, ps0, 2);
            ps1 += __shfl_xor_sync(0xffffffffu, ps1, 1);
            ps1 += __shfl_xor_sync(0xffffffffu, ps1, 2);
            l0 = l0 * a0 + ps0;
            l1 = l1 * a1 + ps1;
            #pragma unroll
            for (int dj = 0; dj < 8; dj++) {
                oacc[dj][0] *= a0; oacc[dj][1] *= a0;
                oacc[dj][2] *= a1; oacc[dj][3] *= a1;
            }
            #pragma unroll
            for (int t = 0; t < 4; t++) {
                uint32_t aH[4], aL[4];
                {
                    bf16 h0,h1,l0b,l1b;
                    split2(sacc[2*t][0],h0,l0b); split2(sacc[2*t][1],h1,l1b);
                    aH[0]=packbf(h0,h1); aL[0]=packbf(l0b,l1b);
                    split2(sacc[2*t][2],h0,l0b); split2(sacc[2*t][3],h1,l1b);
                    aH[1]=packbf(h0,h1); aL[1]=packbf(l0b,l1b);
                    split2(sacc[2*t+1][0],h0,l0b); split2(sacc[2*t+1][1],h1,l1b);
                    aH[2]=packbf(h0,h1); aL[2]=packbf(l0b,l1b);
                    split2(sacc[2*t+1][2],h0,l0b); split2(sacc[2*t+1][3],h1,l1b);
                    aH[3]=packbf(h0,h1); aL[3]=packbf(l0b,l1b);
                }
                // V tile is [seq(k)][dh(n)] row-major -> trans ldmatrix gives B frags
                #pragma unroll
                for (int dj = 0; dj < 8; dj++) {
                    uint32_t vhf[2], vlf[2];
                    uint32_t off = swz((uint32_t)(t*16 + vrow) * 128 + dj*16);
                    LDSM2T(vhf, st + 16384 + off);
                    LDSM2T(vlf, st + 24576 + off);
                    MMA(oacc[dj], aH, vhf);
                    MMA(oacc[dj], aH, vlf);
                    MMA(oacc[dj], aL, vhf);
                }
            }
        }
        __syncthreads();
    }

    float il0 = 1.f / l0, il1 = 1.f / l1;
    size_t row0g = (size_t)bb * SEQ + grow0;
    size_t row1g = (size_t)bb * SEQ + grow1;
    #pragma unroll
    for (int dj = 0; dj < 8; dj++) {
        int col = hd * 64 + dj * 8 + cq;
        float v0 = oacc[dj][0] * il0, v1 = oacc[dj][1] * il0;
        float v2 = oacc[dj][2] * il1, v3 = oacc[dj][3] * il1;
        bf16 h0,h1,lo0,lo1;
        split2(v0,h0,lo0); split2(v1,h1,lo1);
        *(uint32_t*)(ch + row0g * H + col) = packbf(h0,h1);
        *(uint32_t*)(cl + row0g * H + col) = packbf(lo0,lo1);
        split2(v2,h0,lo0); split2(v3,h1,lo1);
        *(uint32_t*)(ch + row1g * H + col) = packbf(h0,h1);
        *(uint32_t*)(cl + row1g * H + col) = packbf(lo0,lo1);
    }
}

// ---------------- split-bf16 mma.sync GEMM (3-stage, 256 threads, r11 cfg) --
// MODE 0: f32+bias | 1: split+bias | 2: gelu split+bias | 3: logits f32 (vocab guard)
template<int MODE>
__global__ __launch_bounds__(256, 1) void gemm_tc(
    const bf16* __restrict__ aH, const bf16* __restrict__ aL,
    const bf16* __restrict__ bH, const bf16* __restrict__ bL,
    const float* __restrict__ bias,
    float* __restrict__ Cf, bf16* __restrict__ Ch, bf16* __restrict__ Cl,
    long long lda, long long ldb, long long ldc, int Ks)
{
    constexpr int BN  = 128;
    constexpr int WN  = BN / 4;
    constexpr int NJ  = WN / 8;
    constexpr int STG = 32768 + 2 * BN * 128;   // 64 KB per stage

    int n0 = blockIdx.x * 128;
    int m0 = blockIdx.y * 128;
    int rowmaxB = 1 << 30;
    aH += (size_t)m0 * lda; aL += (size_t)m0 * lda;
    bH += (size_t)n0 * ldb; bL += (size_t)n0 * ldb;
    if (Cf) Cf += (size_t)m0 * ldc + n0;
    if (Ch) { Ch += (size_t)m0 * ldc + n0; Cl += (size_t)m0 * ldc + n0; }
    if constexpr (MODE == 3) rowmaxB = VOCAB - 1 - n0;

    extern __shared__ char smem[];
    uint32_t sb = sptr(smem);
    int tid = threadIdx.x, wid = tid >> 5, lane = tid & 31;
    int wr = wid >> 2, wc = wid & 3;

    float acc[4][NJ][4];
    #pragma unroll
    for (int i = 0; i < 4; i++)
        #pragma unroll
        for (int j = 0; j < NJ; j++)
            #pragma unroll
            for (int c = 0; c < 4; c++) acc[i][j][c] = 0.f;

    auto prefetch = [&](int t) {
        uint32_t st = sb + (t % 3) * STG;
        #pragma unroll
        for (int i = 0; i < 4; i++) {
            int idx = tid + i * 256;
            int r = idx >> 3, c = idx & 7;
            uint32_t so = swz(r * 128 + c * 16);
            size_t go = (size_t)r * lda + (size_t)t * 64 + c * 8;
            CP16(st + so,         aH + go);
            CP16(st + 16384 + so, aL + go);
        }
        #pragma unroll
        for (int i = 0; i < BN/32; i++) {
            int idx = tid + i * 256;
            int r = idx >> 3, c = idx & 7;
            int rc = r < rowmaxB ? r : rowmaxB;
            uint32_t so = swz(r * 128 + c * 16);
            size_t go = (size_t)rc * ldb + (size_t)t * 64 + c * 8;
            CP16(st + 32768 + so,          bH + go);
            CP16(st + 32768 + BN*128 + so, bL + go);
        }
        CP_COMMIT();
    };

    prefetch(0);
    prefetch(1);
    int arow = lane & 15, asel = lane >> 4;
    int b4row = ((lane >> 4) & 1) * 8 + (lane & 7);
    int b4sel = (lane >> 3) & 1;

    for (int t = 0; t < Ks; t++) {
        if (t + 1 < Ks) CP_WAIT1(); else CP_WAIT0();
        __syncthreads();
        if (t + 2 < Ks) prefetch(t + 2);

        uint32_t sA  = sb + (t % 3) * STG;
        uint32_t sAl = sA + 16384;
        uint32_t sB  = sA + 32768;
        uint32_t sBl = sB + BN * 128;

        #pragma unroll
        for (int kk = 0; kk < 4; kk++) {
            uint32_t ah[4][4], al[4][4], bh[NJ][2], bl[NJ][2];
            #pragma unroll
            for (int mi = 0; mi < 4; mi++) {
                uint32_t off = swz((uint32_t)(wr*64 + mi*16 + arow) * 128 + kk*32 + asel*16);
                LDSM4(ah[mi], sA  + off);
                LDSM4(al[mi], sAl + off);
            }
            #pragma unroll
            for (int p = 0; p < NJ/2; p++) {
                uint32_t rh[4], rl[4];
                uint32_t off = swz((uint32_t)(wc*WN + p*16 + b4row) * 128 + kk*32 + b4sel*16);
                LDSM4(rh, sB  + off);
                LDSM4(rl, sBl + off);
                bh[2*p][0]=rh[0]; bh[2*p][1]=rh[1]; bh[2*p+1][0]=rh[2]; bh[2*p+1][1]=rh[3];
                bl[2*p][0]=rl[0]; bl[2*p][1]=rl[1]; bl[2*p+1][0]=rl[2]; bl[2*p+1][1]=rl[3];
            }
            #pragma unroll
            for (int mi = 0; mi < 4; mi++)
                #pragma unroll
                for (int nj = 0; nj < NJ; nj++) {
                    MMA(acc[mi][nj], ah[mi], bh[nj]);
                    MMA(acc[mi][nj], ah[mi], bl[nj]);
                    MMA(acc[mi][nj], al[mi], bh[nj]);
                }
        }
    }

    int r_lo = lane >> 2, cq = (lane & 3) * 2;
    #pragma unroll
    for (int mi = 0; mi < 4; mi++) {
        #pragma unroll
        for (int nj = 0; nj < NJ; nj++) {
            int cc = wc*WN + nj*8 + cq;
            #pragma unroll
            for (int half = 0; half < 2; half++) {
                int rr = wr*64 + mi*16 + r_lo + half*8;
                float v0 = acc[mi][nj][half*2], v1 = acc[mi][nj][half*2+1];
                if constexpr (MODE == 3) {
                    if (n0 + cc     < VOCAB) Cf[(size_t)rr*ldc + cc]     = v0;
                    if (n0 + cc + 1 < VOCAB) Cf[(size_t)rr*ldc + cc + 1] = v1;
                } else if constexpr (MODE == 0) {
                    v0 += bias[n0 + cc]; v1 += bias[n0 + cc + 1];
                    *(float2*)(Cf + (size_t)rr*ldc + cc) = make_float2(v0, v1);
                } else {
                    v0 += bias[n0 + cc]; v1 += bias[n0 + cc + 1];
                    if constexpr (MODE == 2) { v0 = gelu_exact(v0); v1 = gelu_exact(v1); }
                    bf16 h0,h1,l0,l1;
                    split2(v0,h0,l0); split2(v1,h1,l1);
                    *(uint32_t*)(Ch + (size_t)rr*ldc + cc) = packbf(h0,h1);
                    *(uint32_t*)(Cl + (size_t)rr*ldc + cc) = packbf(l0,l1);
                }
            }
        }
    }
}

// ------------------------------- launch ------------------------------------
#define SMEM128 (3*(32768 + 2*128*128))   // 192 KB, 3-stage
#define SMEMFL  65536

extern "C" void kernel_launch(void* const* d_in, const int* in_sizes, int n_in,
                              void* d_out, int out_size)
{
    const int*   ids  = (const int*)  d_in[0];
    const float* tok  = (const float*)d_in[1];
    const float* pos  = (const float*)d_in[2];
    const float* ln0g = (const float*)d_in[3];
    const float* ln0b = (const float*)d_in[4];
    const float* Wq = (const float*)d_in[5];  const float* bq = (const float*)d_in[6];
    const float* Wk = (const float*)d_in[7];  const float* bk = (const float*)d_in[8];
    const float* Wv = (const float*)d_in[9];  const float* bv = (const float*)d_in[10];
    const float* Wo = (const float*)d_in[11]; const float* bo = (const float*)d_in[12];
    const float* ln1g = (const float*)d_in[13]; const float* ln1b = (const float*)d_in[14];
    const float* Wi = (const float*)d_in[15]; const float* bi = (const float*)d_in[16];
    const float* Wf = (const float*)d_in[17]; const float* bf_ = (const float*)d_in[18];
    const float* ln2g = (const float*)d_in[19]; const float* ln2b = (const float*)d_in[20];
    float* logits = (float*)d_out;

    cudaFuncSetAttribute(gemm_tc<0>, cudaFuncAttributeMaxDynamicSharedMemorySize, SMEM128);
    cudaFuncSetAttribute(gemm_tc<1>, cudaFuncAttributeMaxDynamicSharedMemorySize, SMEM128);
    cudaFuncSetAttribute(gemm_tc<2>, cudaFuncAttributeMaxDynamicSharedMemorySize, SMEM128);
    cudaFuncSetAttribute(gemm_tc<3>, cudaFuncAttributeMaxDynamicSharedMemorySize, SMEM128);
    cudaFuncSetAttribute(flash_kernel, cudaFuncAttributeMaxDynamicSharedMemorySize, SMEMFL);

    float *px, *ptmp, *pbqkv;
    bf16 *pxh, *pxl, *pqkvh, *pqkvl, *pch, *pcl, *phh, *phl;
    bf16 *pwqkvh, *pwqkvl, *pwoh, *pwol;
    bf16 *pwih, *pwil, *pwfh, *pwfl, *ptkh, *ptkl;
    cudaGetSymbolAddress((void**)&px, g_x);      cudaGetSymbolAddress((void**)&ptmp, g_tmp);
    cudaGetSymbolAddress((void**)&pbqkv, g_bqkv);
    cudaGetSymbolAddress((void**)&pxh, x_h);     cudaGetSymbolAddress((void**)&pxl, x_l);
    cudaGetSymbolAddress((void**)&pqkvh, qkv_h); cudaGetSymbolAddress((void**)&pqkvl, qkv_l);
    cudaGetSymbolAddress((void**)&pch, c_h);     cudaGetSymbolAddress((void**)&pcl, c_l);
    cudaGetSymbolAddress((void**)&phh, hh_h);    cudaGetSymbolAddress((void**)&phl, hh_l);
    cudaGetSymbolAddress((void**)&pwqkvh, wqkv_h); cudaGetSymbolAddress((void**)&pwqkvl, wqkv_l);
    cudaGetSymbolAddress((void**)&pwoh, wo_h);   cudaGetSymbolAddress((void**)&pwol, wo_l);
    cudaGetSymbolAddress((void**)&pwih, wi_h);   cudaGetSymbolAddress((void**)&pwil, wi_l);
    cudaGetSymbolAddress((void**)&pwfh, wf_h);   cudaGetSymbolAddress((void**)&pwfl, wf_l);
    cudaGetSymbolAddress((void**)&ptkh, tk_h);   cudaGetSymbolAddress((void**)&ptkl, tk_l);

    // ---- prep ordered so launch #6 (0-based 5) is gemm_tc<1> for ncu ----
    wtransqkv_kernel<<<dim3(16, 16, 18), 256>>>(Wq, Wk, Wv, pwqkvh, pwqkvl);       // 0
    bcat_kernel<<<NLAYER, 1024>>>(bq, bk, bv, pbqkv);                              // 1
    embed_kernel<<<MTOK, 256>>>(ids, tok, pos, ptmp);                              // 2
    ln_kernel<<<MTOK, 256>>>(ptmp, nullptr, ln0g, ln0b, px, pxh, pxl);             // 3
    wtrans_kernel<<<dim3(16, 16, 6), 256>>>(Wo, pwoh, pwol, H, H, (long long)H*H, 0); // 4

    dim3 g_hh(8, 16);
    for (int l = 0; l < NLAYER; l++) {
        size_t oQKV = (size_t)l * H3 * H, oHH = (size_t)l * H * H, oHF = (size_t)l * H * FFD;

        gemm_tc<1><<<dim3(24, 16), 256, SMEM128>>>(pxh, pxl, pwqkvh+oQKV, pwqkvl+oQKV,
                                                   pbqkv + (size_t)l*H3,
                                                   nullptr, pqkvh, pqkvl, H, H, H3, 16);  // 5 on l=0
        if (l == 0) {
            wtrans_kernel<<<dim3(64, 16, 6), 256>>>(Wi, pwih, pwil, H, FFD, (long long)H*FFD, 0);
            wtrans_kernel<<<dim3(16, 64, 6), 256>>>(Wf, pwfh, pwfl, FFD, H, (long long)FFD*H, 0);
            split_kernel<<<2048, 256>>>(tok, ptkh, ptkl, (size_t)VOCAB * H / 4);
        }

        flash_kernel<<<dim3(SEQ/128, BH), 256, SMEMFL>>>(pqkvh, pqkvl, pqkvh + H, pqkvl + H,
                                                         pqkvh + 2*H, pqkvl + 2*H, pch, pcl);

        gemm_tc<0><<<g_hh, 256, SMEM128>>>(pch, pcl, pwoh+oHH, pwol+oHH, bo + (size_t)l*H,
                                           ptmp, nullptr, nullptr, H, H, H, 16);
        ln_kernel<<<MTOK, 256>>>(ptmp, px, ln1g + (size_t)l*H, ln1b + (size_t)l*H, px, pxh, pxl);

        gemm_tc<2><<<dim3(32, 16), 256, SMEM128>>>(pxh, pxl, pwih+oHF, pwil+oHF, bi + (size_t)l*FFD,
                                                   nullptr, phh, phl, H, H, FFD, 16);
        gemm_tc<0><<<g_hh, 256, SMEM128>>>(phh, phl, pwfh+oHF, pwfl+oHF, bf_ + (size_t)l*H,
                                           ptmp, nullptr, nullptr, FFD, FFD, H, 64);
        ln_kernel<<<MTOK, 256>>>(ptmp, px, ln2g + (size_t)l*H, ln2b + (size_t)l*H, px, pxh, pxl);
    }

    gemm_tc<3><<<dim3((VOCAB + 127)/128, 16), 256, SMEM128>>>(
        pxh, pxl, ptkh, ptkl, nullptr, logits, nullptr, nullptr, H, H, VOCAB, 16);
}